// round 15
// baseline (speedup 1.0000x reference)
#include <cuda_runtime.h>
#include <math.h>
#include <stdint.h>

#define SEQ   4096
#define DIN   1024
#define HIDD  1024

// ---------------- scratch (device globals; no allocation allowed) ------------
__device__ float g_qr [SEQ * DIN];
__device__ float g_kr [SEQ * DIN];
__device__ float g_vr [SEQ * DIN];
__device__ float g_WqT[DIN * HIDD];
__device__ float g_WkT[DIN * HIDD];
__device__ float g_WvT[DIN * HIDD];
__device__ float g_Qp [SEQ * HIDD];
__device__ float g_Kp [SEQ * HIDD];
__device__ float g_VpT[HIDD * SEQ];
__device__ float g_Sc [(size_t)SEQ * SEQ];

// ---------------- helpers -----------------------------------------------------
__device__ __forceinline__ float to_tf32(float x) {
    float r; asm("cvt.rna.tf32.f32 %0, %1;" : "=f"(r) : "f"(x)); return r;
}
__device__ __forceinline__ uint32_t smem_u32(const void* p) {
    uint32_t a;
    asm("{ .reg .u64 t; cvta.to.shared.u64 t, %1; cvt.u32.u64 %0, t; }" : "=r"(a) : "l"(p));
    return a;
}
__device__ __forceinline__ void cp16(uint32_t s, const void* g) {
    asm volatile("cp.async.cg.shared.global [%0], [%1], 16;" :: "r"(s), "l"(g));
}
#define CP_COMMIT() asm volatile("cp.async.commit_group;" ::: "memory")
#define CP_WAIT1()  asm volatile("cp.async.wait_group 1;" ::: "memory")
#define CP_WAIT0()  asm volatile("cp.async.wait_group 0;" ::: "memory")

__device__ __forceinline__ void ldsm4(uint32_t& r0, uint32_t& r1, uint32_t& r2,
                                      uint32_t& r3, uint32_t addr) {
    asm volatile("ldmatrix.sync.aligned.m8n8.x4.shared.b16 {%0,%1,%2,%3}, [%4];"
                 : "=r"(r0), "=r"(r1), "=r"(r2), "=r"(r3) : "r"(addr));
}
__device__ __forceinline__ void mma_tf32(float c[4], const uint32_t a[4], const uint32_t b[2]) {
    asm volatile(
        "mma.sync.aligned.m16n8k8.row.col.f32.tf32.tf32.f32 "
        "{%0,%1,%2,%3}, {%4,%5,%6,%7}, {%8,%9}, {%0,%1,%2,%3};\n"
        : "+f"(c[0]), "+f"(c[1]), "+f"(c[2]), "+f"(c[3])
        : "r"(a[0]), "r"(a[1]), "r"(a[2]), "r"(a[3]), "r"(b[0]), "r"(b[1]));
}

// ---------------- tf32 GEMM: C[M,N] = alpha*A[M,K]@B[N,K]^T (+bias) ----------
// 128x128 CTA tile, BK=32, 3-stage cp.async pipeline, ldmatrix feeds.
// 4 warps (128 thr), warp tile 64x64 (2x2 warp grid), 2 CTAs/SM.
// Rationale: halves LDSM bytes per MAC (0.1875 -> 0.125 B/MAC) so the smem
// crossbar (128 B/cyc) stops capping the tensor pipe at ~60%.
#define MT 128
#define NT 128
#define KT 32
#define STG 3
#define SPAD 36                               // floats per smem row (pad)
#define A_WORDS (MT * SPAD)
#define STAGE_BYTES ((MT + NT) * SPAD * 4)    // 36864
#define SM_TOT (STG * STAGE_BYTES)            // 110592

template <bool OUT_T, bool ROUND_OUT>
__global__ __launch_bounds__(128, 2)
void gemm_tf32(const float* __restrict__ A, const float* __restrict__ B,
               const float* __restrict__ bias, float* __restrict__ C,
               int K, int lda, int ldb, int ldc, float alpha)
{
    extern __shared__ char smc[];
    const uint32_t sb = smem_u32(smc);

    const int tid  = threadIdx.x;
    const int warp = tid >> 5;
    const int lane = tid & 31;
    const int m0   = blockIdx.y * MT;
    const int n0   = blockIdx.x * NT;
    const int wm   = (warp >> 1) * 64;        // 2 m-warps
    const int wn   = (warp & 1) * 64;         // 2 n-warps
    const int G    = lane >> 2;
    const int tig  = lane & 3;

    // cp.async chunk mapping: 128 threads -> 16 rows x 8 float4 per iter
    const int cr = tid >> 3;          // row 0..15
    const int cc = (tid & 7) * 4;     // col float 0,4,..28

    // ldmatrix per-thread base word offsets (validated mapping)
    const int a_base = (wm + (lane & 7) + ((lane >> 3) & 1) * 8) * SPAD + (lane >> 4) * 4;
    const int b_base = (wn + (((lane >> 3) >> 1) & 1) * 8 + (lane & 7)) * SPAD
                     + ((lane >> 3) & 1) * 4;

    float c[4][8][4];
    #pragma unroll
    for (int mi = 0; mi < 4; mi++)
        #pragma unroll
        for (int ni = 0; ni < 8; ni++)
            #pragma unroll
            for (int r = 0; r < 4; r++) c[mi][ni][r] = 0.0f;

    const int NC = K / KT;

    auto load_stage = [&](int stage, int kt) {
        const uint32_t sA = sb + stage * STAGE_BYTES;
        const uint32_t sB = sA + A_WORDS * 4;
        #pragma unroll
        for (int i = 0; i < 8; i++) {
            int r = cr + i * 16;
            cp16(sA + (r * SPAD + cc) * 4, A + (size_t)(m0 + r) * lda + kt + cc);
        }
        #pragma unroll
        for (int i = 0; i < 8; i++) {
            int r = cr + i * 16;
            cp16(sB + (r * SPAD + cc) * 4, B + (size_t)(n0 + r) * ldb + kt + cc);
        }
    };

    // prologue: stages 0,1
    load_stage(0, 0);
    CP_COMMIT();
    if (NC > 1) load_stage(1, KT);
    CP_COMMIT();

    for (int ct = 0; ct < NC; ct++) {
        CP_WAIT1();
        __syncthreads();      // stage ct readable; protects ring reuse

        // prefetch ct+2
        if (ct + 2 < NC) load_stage((ct + 2) % STG, (ct + 2) * KT);
        CP_COMMIT();

        const uint32_t sA = sb + (ct % STG) * STAGE_BYTES;
        const uint32_t sB = sA + A_WORDS * 4;

        // --- register-pipelined k-tile: B ping-pong, A rolling refill ---
        uint32_t a[4][4], b[2][8][2];

        // preload k-step 0 fragments
        #pragma unroll
        for (int mi = 0; mi < 4; mi++)
            ldsm4(a[mi][0], a[mi][1], a[mi][2], a[mi][3],
                  sA + (a_base + mi * 16 * SPAD) * 4);
        #pragma unroll
        for (int t = 0; t < 4; t++)
            ldsm4(b[0][2*t][0], b[0][2*t][1], b[0][2*t+1][0], b[0][2*t+1][1],
                  sB + (b_base + t * 16 * SPAD) * 4);

        #pragma unroll
        for (int ks = 0; ks < 4; ks++) {
            const int cur = ks & 1, nxt = cur ^ 1;
            const int ko = (ks + 1) * 8;
            if (ks < 3) {   // prefetch next k-step's B into the other buffer
                #pragma unroll
                for (int t = 0; t < 4; t++)
                    ldsm4(b[nxt][2*t][0], b[nxt][2*t][1],
                          b[nxt][2*t+1][0], b[nxt][2*t+1][1],
                          sB + (b_base + t * 16 * SPAD + ko) * 4);
            }
            #pragma unroll
            for (int mi = 0; mi < 4; mi++) {
                #pragma unroll
                for (int ni = 0; ni < 8; ni++)
                    mma_tf32(c[mi][ni], a[mi], b[cur][ni]);
                if (ks < 3)   // a[mi] dead now -> refill for next k-step
                    ldsm4(a[mi][0], a[mi][1], a[mi][2], a[mi][3],
                          sA + (a_base + mi * 16 * SPAD + ko) * 4);
            }
        }
        // no trailing barrier: next iteration's top barrier orders ring reuse
    }
    CP_WAIT0();

    // epilogue
    #pragma unroll
    for (int mi = 0; mi < 4; mi++) {
        #pragma unroll
        for (int ni = 0; ni < 8; ni++) {
            int row = m0 + wm + mi * 16 + G;
            int col = n0 + wn + ni * 8 + tig * 2;
            float b0 = bias ? bias[col]     : 0.0f;
            float b1 = bias ? bias[col + 1] : 0.0f;
            float v00 = c[mi][ni][0] * alpha + b0;
            float v01 = c[mi][ni][1] * alpha + b1;
            float v10 = c[mi][ni][2] * alpha + b0;
            float v11 = c[mi][ni][3] * alpha + b1;
            if (ROUND_OUT) {
                v00 = to_tf32(v00); v01 = to_tf32(v01);
                v10 = to_tf32(v10); v11 = to_tf32(v11);
            }
            if (!OUT_T) {
                *(float2*)(C + (size_t)row * ldc + col)       = make_float2(v00, v01);
                *(float2*)(C + (size_t)(row + 8) * ldc + col) = make_float2(v10, v11);
            } else {
                C[(size_t)col * ldc + row]           = v00;
                C[(size_t)(col + 1) * ldc + row]     = v01;
                C[(size_t)col * ldc + row + 8]       = v10;
                C[(size_t)(col + 1) * ldc + row + 8] = v11;
            }
        }
    }
}

// ---------------- batched rounding copy: q,k,v in one launch -----------------
__global__ __launch_bounds__(256)
void round_copy3(const float4* __restrict__ q, const float4* __restrict__ k,
                 const float4* __restrict__ v, float4* __restrict__ qr,
                 float4* __restrict__ kr, float4* __restrict__ vr)
{
    const float4* in  = (blockIdx.y == 0) ? q  : (blockIdx.y == 1) ? k  : v;
    float4*       out = (blockIdx.y == 0) ? qr : (blockIdx.y == 1) ? kr : vr;
    int i = blockIdx.x * 256 + threadIdx.x;
    float4 t = in[i];
    t.x = to_tf32(t.x); t.y = to_tf32(t.y); t.z = to_tf32(t.z); t.w = to_tf32(t.w);
    out[i] = t;
}

// ---------------- batched 1024x1024 transpose + round ------------------------
__global__ __launch_bounds__(256)
void transpose_round3(const float* __restrict__ Wq, const float* __restrict__ Wk,
                      const float* __restrict__ Wv, float* __restrict__ WqT,
                      float* __restrict__ WkT, float* __restrict__ WvT)
{
    __shared__ float t[32][33];
    const float* in  = (blockIdx.z == 0) ? Wq  : (blockIdx.z == 1) ? Wk  : Wv;
    float*       out = (blockIdx.z == 0) ? WqT : (blockIdx.z == 1) ? WkT : WvT;
    const int bx = blockIdx.x * 32, by = blockIdx.y * 32;
    #pragma unroll
    for (int j = 0; j < 32; j += 8)
        t[threadIdx.y + j][threadIdx.x] =
            in[(size_t)(by + threadIdx.y + j) * 1024 + bx + threadIdx.x];
    __syncthreads();
    #pragma unroll
    for (int j = 0; j < 32; j += 8)
        out[(size_t)(bx + threadIdx.y + j) * 1024 + by + threadIdx.x] =
            to_tf32(t[threadIdx.x][threadIdx.y + j]);
}

// ---------------- row softmax over [SEQ, SEQ], in place (256 threads!) -------
__global__ __launch_bounds__(256)
void softmax_rows(float* __restrict__ Sc)
{
    __shared__ float red[8];
    const int row = blockIdx.x;
    const int tid = threadIdx.x;
    const int lane = tid & 31;
    const int warp = tid >> 5;

    float4* p4 = (float4*)(Sc + (size_t)row * SEQ);

    float4 v[4];
    float lmax = -INFINITY;
    #pragma unroll
    for (int i = 0; i < 4; i++) {
        v[i] = p4[tid + i * 256];
        lmax = fmaxf(lmax, fmaxf(fmaxf(v[i].x, v[i].y), fmaxf(v[i].z, v[i].w)));
    }
    #pragma unroll
    for (int o = 16; o > 0; o >>= 1)
        lmax = fmaxf(lmax, __shfl_xor_sync(0xffffffffu, lmax, o));
    if (lane == 0) red[warp] = lmax;
    __syncthreads();
    float rmax = red[0];
    #pragma unroll
    for (int w = 1; w < 8; w++) rmax = fmaxf(rmax, red[w]);

    float lsum = 0.0f;
    #pragma unroll
    for (int i = 0; i < 4; i++) {
        v[i].x = __expf(v[i].x - rmax);
        v[i].y = __expf(v[i].y - rmax);
        v[i].z = __expf(v[i].z - rmax);
        v[i].w = __expf(v[i].w - rmax);
        lsum += v[i].x + v[i].y + v[i].z + v[i].w;
    }
    #pragma unroll
    for (int o = 16; o > 0; o >>= 1)
        lsum += __shfl_xor_sync(0xffffffffu, lsum, o);
    __syncthreads();
    if (lane == 0) red[warp] = lsum;
    __syncthreads();
    float rsum = 0.0f;
    #pragma unroll
    for (int w = 0; w < 8; w++) rsum += red[w];
    float inv = 1.0f / rsum;

    #pragma unroll
    for (int i = 0; i < 4; i++) {
        v[i].x = to_tf32(v[i].x * inv);
        v[i].y = to_tf32(v[i].y * inv);
        v[i].z = to_tf32(v[i].z * inv);
        v[i].w = to_tf32(v[i].w * inv);
        p4[tid + i * 256] = v[i];
    }
}

// ---------------- launch ------------------------------------------------------
extern "C" void kernel_launch(void* const* d_in, const int* in_sizes, int n_in,
                              void* d_out, int out_size)
{
    (void)in_sizes; (void)n_in; (void)out_size;

    const float* q  = (const float*)d_in[0];
    const float* k  = (const float*)d_in[1];
    const float* v  = (const float*)d_in[2];
    const float* Wq = (const float*)d_in[3];
    const float* bq = (const float*)d_in[4];
    const float* Wk = (const float*)d_in[5];
    const float* bk = (const float*)d_in[6];
    const float* Wv = (const float*)d_in[7];
    const float* bv = (const float*)d_in[8];
    float* out = (float*)d_out;

    void* p;
    cudaGetSymbolAddress(&p, g_qr);  float* qr  = (float*)p;
    cudaGetSymbolAddress(&p, g_kr);  float* kr  = (float*)p;
    cudaGetSymbolAddress(&p, g_vr);  float* vr  = (float*)p;
    cudaGetSymbolAddress(&p, g_WqT); float* WqT = (float*)p;
    cudaGetSymbolAddress(&p, g_WkT); float* WkT = (float*)p;
    cudaGetSymbolAddress(&p, g_WvT); float* WvT = (float*)p;
    cudaGetSymbolAddress(&p, g_Qp);  float* Qp  = (float*)p;
    cudaGetSymbolAddress(&p, g_Kp);  float* Kp  = (float*)p;
    cudaGetSymbolAddress(&p, g_VpT); float* VpT = (float*)p;
    cudaGetSymbolAddress(&p, g_Sc);  float* Sc  = (float*)p;

    cudaFuncSetAttribute((const void*)gemm_tf32<false, false>,
                         cudaFuncAttributeMaxDynamicSharedMemorySize, SM_TOT);
    cudaFuncSetAttribute((const void*)gemm_tf32<false, true>,
                         cudaFuncAttributeMaxDynamicSharedMemorySize, SM_TOT);
    cudaFuncSetAttribute((const void*)gemm_tf32<true, true>,
                         cudaFuncAttributeMaxDynamicSharedMemorySize, SM_TOT);

    // launch 0: pre-round q,k,v to tf32 (batched)
    const int n4 = SEQ * DIN / 4;
    round_copy3<<<dim3(n4 / 256, 3), 256>>>((const float4*)q, (const float4*)k,
                                            (const float4*)v, (float4*)qr,
                                            (float4*)kr, (float4*)vr);

    // launch 1: transpose + round all three weight matrices (batched)
    transpose_round3<<<dim3(32, 32, 3), dim3(32, 8)>>>(Wq, Wk, Wv, WqT, WkT, WvT);

    const dim3 gblk(128);               // GEMM kernels ONLY (4 warps)
    dim3 gproj(HIDD / NT, SEQ / MT);    // 8 x 32
    dim3 gsc(SEQ / NT, SEQ / MT);       // 32 x 32
    dim3 gctx(HIDD / NT, SEQ / MT);     // 8 x 32

    // launches 2-4: projections (outputs tf32-rounded)
    gemm_tf32<false, true><<<gproj, gblk, SM_TOT>>>(qr, WqT, bq, Qp,  DIN, DIN, DIN, HIDD, 1.0f);
    gemm_tf32<false, true><<<gproj, gblk, SM_TOT>>>(kr, WkT, bk, Kp,  DIN, DIN, DIN, HIDD, 1.0f);
    gemm_tf32<true,  true><<<gproj, gblk, SM_TOT>>>(vr, WvT, bv, VpT, DIN, DIN, DIN, SEQ,  1.0f);

    // launch 5: scores = Qp @ Kp^T / 32   (ncu -s 5 -c 1 captures THIS)
    gemm_tf32<false, false><<<gsc, gblk, SM_TOT>>>(Qp, Kp, (const float*)nullptr, Sc,
                                                   HIDD, HIDD, HIDD, SEQ, 0.03125f);

    // launch 6: softmax — MUST be 256 threads (kernel is hard-coded for it)
    softmax_rows<<<SEQ, 256>>>(Sc);

    // launch 7: context = softmax(Sc) @ VpT^T
    gemm_tf32<false, false><<<gctx, gblk, SM_TOT>>>(Sc, VpT, (const float*)nullptr, out,
                                                    SEQ, SEQ, SEQ, HIDD, 1.0f);
}

// round 16
// speedup vs baseline: 1.0394x; 1.0394x over previous
#include <cuda_runtime.h>
#include <math.h>
#include <stdint.h>

#define SEQ   4096
#define DIN   1024
#define HIDD  1024

// ---------------- scratch (device globals; no allocation allowed) ------------
__device__ float g_qr [SEQ * DIN];
__device__ float g_kr [SEQ * DIN];
__device__ float g_vr [SEQ * DIN];
__device__ float g_WqT[DIN * HIDD];
__device__ float g_WkT[DIN * HIDD];
__device__ float g_WvT[DIN * HIDD];
__device__ float g_Qp [SEQ * HIDD];
__device__ float g_Kp [SEQ * HIDD];
__device__ float g_VpT[HIDD * SEQ];
__device__ float g_Sc [(size_t)SEQ * SEQ];

// ---------------- helpers -----------------------------------------------------
__device__ __forceinline__ float to_tf32(float x) {
    float r; asm("cvt.rna.tf32.f32 %0, %1;" : "=f"(r) : "f"(x)); return r;
}
__device__ __forceinline__ uint32_t smem_u32(const void* p) {
    uint32_t a;
    asm("{ .reg .u64 t; cvta.to.shared.u64 t, %1; cvt.u32.u64 %0, t; }" : "=r"(a) : "l"(p));
    return a;
}
__device__ __forceinline__ void cp16(uint32_t s, const void* g) {
    asm volatile("cp.async.cg.shared.global [%0], [%1], 16;" :: "r"(s), "l"(g));
}
#define CP_COMMIT() asm volatile("cp.async.commit_group;" ::: "memory")
#define CP_WAIT1()  asm volatile("cp.async.wait_group 1;" ::: "memory")
#define CP_WAIT0()  asm volatile("cp.async.wait_group 0;" ::: "memory")

__device__ __forceinline__ void ldsm4(uint32_t& r0, uint32_t& r1, uint32_t& r2,
                                      uint32_t& r3, uint32_t addr) {
    asm volatile("ldmatrix.sync.aligned.m8n8.x4.shared.b16 {%0,%1,%2,%3}, [%4];"
                 : "=r"(r0), "=r"(r1), "=r"(r2), "=r"(r3) : "r"(addr));
}
__device__ __forceinline__ void mma_tf32(float c[4], const uint32_t a[4], const uint32_t b[2]) {
    asm volatile(
        "mma.sync.aligned.m16n8k8.row.col.f32.tf32.tf32.f32 "
        "{%0,%1,%2,%3}, {%4,%5,%6,%7}, {%8,%9}, {%0,%1,%2,%3};\n"
        : "+f"(c[0]), "+f"(c[1]), "+f"(c[2]), "+f"(c[3])
        : "r"(a[0]), "r"(a[1]), "r"(a[2]), "r"(a[3]), "r"(b[0]), "r"(b[1]));
}

// ---------------- tf32 GEMM body: C = alpha*A[M,K]@B[N,K]^T (+bias) ----------
// 128x128 CTA tile, BK=32, 3-stage cp.async pipeline, ldmatrix feeds,
// register pipeline (B ping-pong + A rolling refill).
// 8 warps (256 thr), warp tile 64x32, 2 CTAs/SM.  [R12 best config]
#define MT 128
#define NT 128
#define KT 32
#define STG 3
#define SPAD 36                               // floats per smem row (pad)
#define A_WORDS (MT * SPAD)
#define STAGE_BYTES ((MT + NT) * SPAD * 4)    // 36864
#define SM_TOT (STG * STAGE_BYTES)            // 110592

template <bool ROUND_OUT>
__device__ __forceinline__ void gemm_body(
    const float* __restrict__ A, const float* __restrict__ B,
    const float* __restrict__ bias, float* __restrict__ C,
    int K, int lda, int ldb, int ldc, float alpha, bool out_t, char* smc)
{
    const uint32_t sb = smem_u32(smc);

    const int tid  = threadIdx.x;
    const int warp = tid >> 5;
    const int lane = tid & 31;
    const int m0   = blockIdx.y * MT;
    const int n0   = blockIdx.x * NT;
    const int wm   = (warp >> 2) * 64;
    const int wn   = (warp & 3) * 32;
    const int G    = lane >> 2;
    const int tig  = lane & 3;

    // cp.async chunk mapping (per 128x32 tile: 1024 16B chunks, 4/thread)
    const int cr = tid >> 3;          // row 0..31
    const int cc = (tid & 7) * 4;     // col float 0,4,..28

    // ldmatrix per-thread base word offsets (validated mapping)
    const int a_base = (wm + (lane & 7) + ((lane >> 3) & 1) * 8) * SPAD + (lane >> 4) * 4;
    const int b_base = (wn + (((lane >> 3) >> 1) & 1) * 8 + (lane & 7)) * SPAD
                     + ((lane >> 3) & 1) * 4;

    float c[4][4][4];
    #pragma unroll
    for (int mi = 0; mi < 4; mi++)
        #pragma unroll
        for (int ni = 0; ni < 4; ni++)
            #pragma unroll
            for (int r = 0; r < 4; r++) c[mi][ni][r] = 0.0f;

    const int NC = K / KT;

    auto load_stage = [&](int stage, int kt) {
        const uint32_t sA = sb + stage * STAGE_BYTES;
        const uint32_t sB = sA + A_WORDS * 4;
        #pragma unroll
        for (int i = 0; i < 4; i++) {
            int r = cr + i * 32;
            cp16(sA + (r * SPAD + cc) * 4, A + (size_t)(m0 + r) * lda + kt + cc);
        }
        #pragma unroll
        for (int i = 0; i < 4; i++) {
            int r = cr + i * 32;
            cp16(sB + (r * SPAD + cc) * 4, B + (size_t)(n0 + r) * ldb + kt + cc);
        }
    };

    // prologue: stages 0,1
    load_stage(0, 0);
    CP_COMMIT();
    if (NC > 1) load_stage(1, KT);
    CP_COMMIT();

    for (int ct = 0; ct < NC; ct++) {
        CP_WAIT1();
        __syncthreads();      // stage ct readable; protects ring reuse

        if (ct + 2 < NC) load_stage((ct + 2) % STG, (ct + 2) * KT);
        CP_COMMIT();

        const uint32_t sA = sb + (ct % STG) * STAGE_BYTES;
        const uint32_t sB = sA + A_WORDS * 4;

        // --- register-pipelined k-tile: B ping-pong, A rolling refill ---
        uint32_t a[4][4], b[2][4][2];

        #pragma unroll
        for (int mi = 0; mi < 4; mi++)
            ldsm4(a[mi][0], a[mi][1], a[mi][2], a[mi][3],
                  sA + (a_base + mi * 16 * SPAD) * 4);
        ldsm4(b[0][0][0], b[0][0][1], b[0][1][0], b[0][1][1], sB + b_base * 4);
        ldsm4(b[0][2][0], b[0][2][1], b[0][3][0], b[0][3][1],
              sB + (b_base + 16 * SPAD) * 4);

        #pragma unroll
        for (int ks = 0; ks < 4; ks++) {
            const int cur = ks & 1, nxt = cur ^ 1;
            const int ko = (ks + 1) * 8;
            if (ks < 3) {
                ldsm4(b[nxt][0][0], b[nxt][0][1], b[nxt][1][0], b[nxt][1][1],
                      sB + (b_base + ko) * 4);
                ldsm4(b[nxt][2][0], b[nxt][2][1], b[nxt][3][0], b[nxt][3][1],
                      sB + (b_base + 16 * SPAD + ko) * 4);
            }
            #pragma unroll
            for (int mi = 0; mi < 4; mi++) {
                #pragma unroll
                for (int ni = 0; ni < 4; ni++)
                    mma_tf32(c[mi][ni], a[mi], b[cur][ni]);
                if (ks < 3)
                    ldsm4(a[mi][0], a[mi][1], a[mi][2], a[mi][3],
                          sA + (a_base + mi * 16 * SPAD + ko) * 4);
            }
        }
        // no trailing barrier: next iteration's top barrier orders ring reuse
    }
    CP_WAIT0();

    // epilogue (out_t is block-uniform; no divergence)
    #pragma unroll
    for (int mi = 0; mi < 4; mi++) {
        #pragma unroll
        for (int ni = 0; ni < 4; ni++) {
            int row = m0 + wm + mi * 16 + G;
            int col = n0 + wn + ni * 8 + tig * 2;
            float b0 = bias ? bias[col]     : 0.0f;
            float b1 = bias ? bias[col + 1] : 0.0f;
            float v00 = c[mi][ni][0] * alpha + b0;
            float v01 = c[mi][ni][1] * alpha + b1;
            float v10 = c[mi][ni][2] * alpha + b0;
            float v11 = c[mi][ni][3] * alpha + b1;
            if (ROUND_OUT) {
                v00 = to_tf32(v00); v01 = to_tf32(v01);
                v10 = to_tf32(v10); v11 = to_tf32(v11);
            }
            if (!out_t) {
                *(float2*)(C + (size_t)row * ldc + col)       = make_float2(v00, v01);
                *(float2*)(C + (size_t)(row + 8) * ldc + col) = make_float2(v10, v11);
            } else {
                C[(size_t)col * ldc + row]           = v00;
                C[(size_t)(col + 1) * ldc + row]     = v01;
                C[(size_t)col * ldc + row + 8]       = v10;
                C[(size_t)(col + 1) * ldc + row + 8] = v11;
            }
        }
    }
}

// plain GEMM entry (scores / context)
template <bool ROUND_OUT>
__global__ __launch_bounds__(256, 2)
void gemm_tf32(const float* __restrict__ A, const float* __restrict__ B,
               const float* __restrict__ bias, float* __restrict__ C,
               int K, int lda, int ldb, int ldc, float alpha)
{
    extern __shared__ char smc[];
    gemm_body<ROUND_OUT>(A, B, bias, C, K, lda, ldb, ldc, alpha, false, smc);
}

// batched projection entry: z=0 -> Qp, z=1 -> Kp, z=2 -> VpT (transposed store)
__global__ __launch_bounds__(256, 2)
void proj3_tf32(const float* __restrict__ qr, const float* __restrict__ kr,
                const float* __restrict__ vr,
                const float* __restrict__ WqT, const float* __restrict__ WkT,
                const float* __restrict__ WvT,
                const float* __restrict__ bq, const float* __restrict__ bk,
                const float* __restrict__ bv,
                float* __restrict__ Qp, float* __restrict__ Kp,
                float* __restrict__ VpT)
{
    extern __shared__ char smc[];
    const int z = blockIdx.z;
    const float* A    = (z == 0) ? qr  : (z == 1) ? kr  : vr;
    const float* B    = (z == 0) ? WqT : (z == 1) ? WkT : WvT;
    const float* bias = (z == 0) ? bq  : (z == 1) ? bk  : bv;
    float*       C    = (z == 0) ? Qp  : (z == 1) ? Kp  : VpT;
    const bool  out_t = (z == 2);
    const int   ldc   = out_t ? SEQ : HIDD;
    gemm_body<true>(A, B, bias, C, DIN, DIN, DIN, ldc, 1.0f, out_t, smc);
}

// ---------------- batched rounding copy: q,k,v in one launch -----------------
__global__ __launch_bounds__(256)
void round_copy3(const float4* __restrict__ q, const float4* __restrict__ k,
                 const float4* __restrict__ v, float4* __restrict__ qr,
                 float4* __restrict__ kr, float4* __restrict__ vr)
{
    const float4* in  = (blockIdx.y == 0) ? q  : (blockIdx.y == 1) ? k  : v;
    float4*       out = (blockIdx.y == 0) ? qr : (blockIdx.y == 1) ? kr : vr;
    int i = blockIdx.x * 256 + threadIdx.x;
    float4 t = in[i];
    t.x = to_tf32(t.x); t.y = to_tf32(t.y); t.z = to_tf32(t.z); t.w = to_tf32(t.w);
    out[i] = t;
}

// ---------------- batched 1024x1024 transpose + round ------------------------
__global__ __launch_bounds__(256)
void transpose_round3(const float* __restrict__ Wq, const float* __restrict__ Wk,
                      const float* __restrict__ Wv, float* __restrict__ WqT,
                      float* __restrict__ WkT, float* __restrict__ WvT)
{
    __shared__ float t[32][33];
    const float* in  = (blockIdx.z == 0) ? Wq  : (blockIdx.z == 1) ? Wk  : Wv;
    float*       out = (blockIdx.z == 0) ? WqT : (blockIdx.z == 1) ? WkT : WvT;
    const int bx = blockIdx.x * 32, by = blockIdx.y * 32;
    #pragma unroll
    for (int j = 0; j < 32; j += 8)
        t[threadIdx.y + j][threadIdx.x] =
            in[(size_t)(by + threadIdx.y + j) * 1024 + bx + threadIdx.x];
    __syncthreads();
    #pragma unroll
    for (int j = 0; j < 32; j += 8)
        out[(size_t)(bx + threadIdx.y + j) * 1024 + by + threadIdx.x] =
            to_tf32(t[threadIdx.x][threadIdx.y + j]);
}

// ---------------- row softmax over [SEQ, SEQ], in place (256 threads!) -------
__global__ __launch_bounds__(256)
void softmax_rows(float* __restrict__ Sc)
{
    __shared__ float red[8];
    const int row = blockIdx.x;
    const int tid = threadIdx.x;
    const int lane = tid & 31;
    const int warp = tid >> 5;

    float4* p4 = (float4*)(Sc + (size_t)row * SEQ);

    float4 v[4];
    float lmax = -INFINITY;
    #pragma unroll
    for (int i = 0; i < 4; i++) {
        v[i] = p4[tid + i * 256];
        lmax = fmaxf(lmax, fmaxf(fmaxf(v[i].x, v[i].y), fmaxf(v[i].z, v[i].w)));
    }
    #pragma unroll
    for (int o = 16; o > 0; o >>= 1)
        lmax = fmaxf(lmax, __shfl_xor_sync(0xffffffffu, lmax, o));
    if (lane == 0) red[warp] = lmax;
    __syncthreads();
    float rmax = red[0];
    #pragma unroll
    for (int w = 1; w < 8; w++) rmax = fmaxf(rmax, red[w]);

    float lsum = 0.0f;
    #pragma unroll
    for (int i = 0; i < 4; i++) {
        v[i].x = __expf(v[i].x - rmax);
        v[i].y = __expf(v[i].y - rmax);
        v[i].z = __expf(v[i].z - rmax);
        v[i].w = __expf(v[i].w - rmax);
        lsum += v[i].x + v[i].y + v[i].z + v[i].w;
    }
    #pragma unroll
    for (int o = 16; o > 0; o >>= 1)
        lsum += __shfl_xor_sync(0xffffffffu, lsum, o);
    __syncthreads();
    if (lane == 0) red[warp] = lsum;
    __syncthreads();
    float rsum = 0.0f;
    #pragma unroll
    for (int w = 0; w < 8; w++) rsum += red[w];
    float inv = 1.0f / rsum;

    #pragma unroll
    for (int i = 0; i < 4; i++) {
        v[i].x = to_tf32(v[i].x * inv);
        v[i].y = to_tf32(v[i].y * inv);
        v[i].z = to_tf32(v[i].z * inv);
        v[i].w = to_tf32(v[i].w * inv);
        p4[tid + i * 256] = v[i];
    }
}

// ---------------- launch ------------------------------------------------------
extern "C" void kernel_launch(void* const* d_in, const int* in_sizes, int n_in,
                              void* d_out, int out_size)
{
    (void)in_sizes; (void)n_in; (void)out_size;

    const float* q  = (const float*)d_in[0];
    const float* k  = (const float*)d_in[1];
    const float* v  = (const float*)d_in[2];
    const float* Wq = (const float*)d_in[3];
    const float* bq = (const float*)d_in[4];
    const float* Wk = (const float*)d_in[5];
    const float* bk = (const float*)d_in[6];
    const float* Wv = (const float*)d_in[7];
    const float* bv = (const float*)d_in[8];
    float* out = (float*)d_out;

    void* p;
    cudaGetSymbolAddress(&p, g_qr);  float* qr  = (float*)p;
    cudaGetSymbolAddress(&p, g_kr);  float* kr  = (float*)p;
    cudaGetSymbolAddress(&p, g_vr);  float* vr  = (float*)p;
    cudaGetSymbolAddress(&p, g_WqT); float* WqT = (float*)p;
    cudaGetSymbolAddress(&p, g_WkT); float* WkT = (float*)p;
    cudaGetSymbolAddress(&p, g_WvT); float* WvT = (float*)p;
    cudaGetSymbolAddress(&p, g_Qp);  float* Qp  = (float*)p;
    cudaGetSymbolAddress(&p, g_Kp);  float* Kp  = (float*)p;
    cudaGetSymbolAddress(&p, g_VpT); float* VpT = (float*)p;
    cudaGetSymbolAddress(&p, g_Sc);  float* Sc  = (float*)p;

    cudaFuncSetAttribute((const void*)gemm_tf32<false>,
                         cudaFuncAttributeMaxDynamicSharedMemorySize, SM_TOT);
    cudaFuncSetAttribute((const void*)proj3_tf32,
                         cudaFuncAttributeMaxDynamicSharedMemorySize, SM_TOT);

    // launch 0: pre-round q,k,v to tf32 (batched)
    const int n4 = SEQ * DIN / 4;
    round_copy3<<<dim3(n4 / 256, 3), 256>>>((const float4*)q, (const float4*)k,
                                            (const float4*)v, (float4*)qr,
                                            (float4*)kr, (float4*)vr);

    // launch 1: transpose + round all three weight matrices (batched)
    transpose_round3<<<dim3(32, 32, 3), dim3(32, 8)>>>(Wq, Wk, Wv, WqT, WkT, WvT);

    // launch 2: all three projections in ONE launch (768 CTAs)
    dim3 gproj(HIDD / NT, SEQ / MT, 3);    // 8 x 32 x 3
    proj3_tf32<<<gproj, 256, SM_TOT>>>(qr, kr, vr, WqT, WkT, WvT,
                                       bq, bk, bv, Qp, Kp, VpT);

    // launch 3: scores = Qp @ Kp^T / 32
    dim3 gsc(SEQ / NT, SEQ / MT);          // 32 x 32
    gemm_tf32<false><<<gsc, 256, SM_TOT>>>(Qp, Kp, (const float*)nullptr, Sc,
                                           HIDD, HIDD, HIDD, SEQ, 0.03125f);

    // launch 4: softmax (256 threads, hard requirement)
    softmax_rows<<<SEQ, 256>>>(Sc);

    // launch 5: context = softmax(Sc) @ VpT^T   (ncu -s 5 captures THIS now)
    dim3 gctx(HIDD / NT, SEQ / MT);        // 8 x 32
    gemm_tf32<false><<<gctx, 256, SM_TOT>>>(Sc, VpT, (const float*)nullptr, out,
                                            SEQ, SEQ, SEQ, HIDD, 1.0f);
}